// round 13
// baseline (speedup 1.0000x reference)
#include <cuda_runtime.h>
#include <cuda_bf16.h>
#include <cstdint>

// Problem constants
#define T_STEPS 512
#define BATCH   256
#define D_IN    512
#define HID     128
#define G4      512   // 4*H
#define YS_ELEMS (T_STEPS * BATCH * HID)
#define M_TOTAL  (T_STEPS * BATCH)        // 131072

typedef unsigned long long ull;

// ---------------- device scratch (static; allowed) ----------------
__device__ float          g_xpre  [(size_t)M_TOTAL * G4];      // 256 MB
__device__ __nv_bfloat16  g_obs_hi[(size_t)M_TOTAL * D_IN];    // 128 MB
__device__ __nv_bfloat16  g_obs_lo[(size_t)M_TOTAL * D_IN];    // 128 MB
__device__ __nv_bfloat16  g_wiT_hi[(size_t)G4 * D_IN];         // [n][k]
__device__ __nv_bfloat16  g_wiT_lo[(size_t)G4 * D_IN];

// ---------------- small helpers ----------------
__device__ __forceinline__ ull fpack2(float lo, float hi) {
    ull r; asm("mov.b64 %0, {%1, %2};" : "=l"(r) : "f"(lo), "f"(hi)); return r;
}
__device__ __forceinline__ ull ffma2(ull a, ull b, ull c) {
    ull d; asm("fma.rn.f32x2 %0, %1, %2, %3;" : "=l"(d) : "l"(a), "l"(b), "l"(c)); return d;
}
__device__ __forceinline__ ull fadd2(ull a, ull b) {
    ull d; asm("add.rn.f32x2 %0, %1, %2;" : "=l"(d) : "l"(a), "l"(b)); return d;
}
__device__ __forceinline__ float funpack_add(ull p) {
    float lo, hi; asm("mov.b64 {%0, %1}, %2;" : "=f"(lo), "=f"(hi) : "l"(p));
    return lo + hi;
}
__device__ __forceinline__ float sigm_(float x) {
    return __fdividef(1.0f, 1.0f + __expf(-x));
}
__device__ __forceinline__ float tanh_(float x) {
    float e = __expf(-2.0f * x);
    return __fdividef(1.0f - e, 1.0f + e);
}
__device__ __forceinline__ uint32_t smem_u32(const void* p) {
    uint32_t a;
    asm("{ .reg .u64 t; cvta.to.shared.u64 t, %1; cvt.u32.u64 %0, t; }" : "=r"(a) : "l"(p));
    return a;
}

// SW128 swizzle (byte offsets within a 128B-row tile)
#define SWZ128(o) ((o) ^ (((o) >> 3) & 0x70))

__device__ __forceinline__ void cpasync16(uint32_t s, const void* g) {
    asm volatile("cp.async.cg.shared.global [%0], [%1], 16;" :: "r"(s), "l"(g));
}
__device__ __forceinline__ void ldsm_x4(uint32_t* r, uint32_t addr) {
    asm volatile("ldmatrix.sync.aligned.m8n8.x4.shared.b16 {%0,%1,%2,%3}, [%4];"
        : "=r"(r[0]), "=r"(r[1]), "=r"(r[2]), "=r"(r[3]) : "r"(addr));
}
__device__ __forceinline__ void mma16816(float* c, const uint32_t* a, const uint32_t* b) {
    asm volatile("mma.sync.aligned.m16n8k16.row.col.f32.bf16.bf16.f32 "
        "{%0,%1,%2,%3}, {%4,%5,%6,%7}, {%8,%9}, {%0,%1,%2,%3};"
        : "+f"(c[0]), "+f"(c[1]), "+f"(c[2]), "+f"(c[3])
        : "r"(a[0]), "r"(a[1]), "r"(a[2]), "r"(a[3]), "r"(b[0]), "r"(b[1]));
}

// ============================================================
// Prep 1: split obs fp32 -> bf16 hi/lo (pure bandwidth)
// ============================================================
__global__ __launch_bounds__(256)
void split_obs_kernel(const float* __restrict__ obs) {
    size_t n4 = (size_t)M_TOTAL * D_IN / 4;
    size_t stride = (size_t)gridDim.x * blockDim.x;
    for (size_t i = (size_t)blockIdx.x * blockDim.x + threadIdx.x; i < n4; i += stride) {
        float4 v = ((const float4*)obs)[i];
        __nv_bfloat16 h0 = __float2bfloat16(v.x);
        __nv_bfloat16 h1 = __float2bfloat16(v.y);
        __nv_bfloat16 h2 = __float2bfloat16(v.z);
        __nv_bfloat16 h3 = __float2bfloat16(v.w);
        __nv_bfloat16 l0 = __float2bfloat16(v.x - __bfloat162float(h0));
        __nv_bfloat16 l1 = __float2bfloat16(v.y - __bfloat162float(h1));
        __nv_bfloat16 l2 = __float2bfloat16(v.z - __bfloat162float(h2));
        __nv_bfloat16 l3 = __float2bfloat16(v.w - __bfloat162float(h3));
        ((__nv_bfloat162*)g_obs_hi)[2 * i]     = __nv_bfloat162(h0, h1);
        ((__nv_bfloat162*)g_obs_hi)[2 * i + 1] = __nv_bfloat162(h2, h3);
        ((__nv_bfloat162*)g_obs_lo)[2 * i]     = __nv_bfloat162(l0, l1);
        ((__nv_bfloat162*)g_obs_lo)[2 * i + 1] = __nv_bfloat162(l2, l3);
    }
}

// ============================================================
// Prep 2: transpose + split Wi [k][n] -> WiT hi/lo [n][k]
// ============================================================
__global__ __launch_bounds__(256)
void split_wiT_kernel(const float* __restrict__ Wi) {
    int idx = blockIdx.x * blockDim.x + threadIdx.x;
    if (idx < G4 * D_IN) {
        int n = idx >> 9, k = idx & 511;
        float v = Wi[k * G4 + n];
        __nv_bfloat16 h = __float2bfloat16(v);
        __nv_bfloat16 l = __float2bfloat16(v - __bfloat162float(h));
        g_wiT_hi[idx] = h;
        g_wiT_lo[idx] = l;
    }
}

// ============================================================
// GEMM via mma.sync bf16-split (Ah*Bh + Ah*Bl + Al*Bh, fp32 acc)
// v3: 3-stage cp.async pipeline, ONE __syncthreads per k-chunk.
//   BM=128 BN=128, 8 warps, warp tile 32m x 64n.
//   stage = Ah 16K | Al 16K | Bh 16K | Bl 16K = 64KB; 3 stages.
// ============================================================
#define GSTAGE 65536
#define GSM_TOTAL (3 * GSTAGE)     // 196608

__global__ __launch_bounds__(256, 1)
void gemm_hmma_kernel(const float* __restrict__ bias)
{
    extern __shared__ __align__(1024) char smem[];
    const uint32_t smb = smem_u32(smem);
    const int tid = threadIdx.x;
    const int warp = tid >> 5, lane = tid & 31;
    const int bn = blockIdx.x;     // 0..3
    const int bm = blockIdx.y;     // 0..1023

    const __nv_bfloat16* Agh = g_obs_hi + (size_t)bm * 128 * 512;
    const __nv_bfloat16* Agl = g_obs_lo + (size_t)bm * 128 * 512;
    const __nv_bfloat16* Bgh = g_wiT_hi + (size_t)bn * 128 * 512;
    const __nv_bfloat16* Bgl = g_wiT_lo + (size_t)bn * 128 * 512;

    auto load_stage = [&](int kc, int s) {
        const __nv_bfloat16* srcs[4] = {Agh, Agl, Bgh, Bgl};
        uint32_t sb = smb + s * GSTAGE;
#pragma unroll
        for (int tile = 0; tile < 4; tile++) {
            const __nv_bfloat16* src = srcs[tile];
            uint32_t tb = sb + tile * 16384;
#pragma unroll
            for (int t = 0; t < 4; t++) {
                int i = tid + t * 256;
                int row = i >> 3, cc = i & 7;
                uint32_t so = tb + SWZ128((uint32_t)(row * 128 + cc * 16));
                cpasync16(so, src + (size_t)row * 512 + kc * 64 + cc * 8);
            }
        }
        asm volatile("cp.async.commit_group;" ::: "memory");
    };

    const int wm = (warp & 3) * 32;
    const int wn = (warp >> 2) * 64;
    const int lr = lane & 7, g = lane >> 3;

    float acc[2][8][4];
#pragma unroll
    for (int i = 0; i < 2; i++)
#pragma unroll
        for (int j = 0; j < 8; j++)
#pragma unroll
            for (int q = 0; q < 4; q++) acc[i][j][q] = 0.0f;

    load_stage(0, 0);
    load_stage(1, 1);

    for (int kc = 0; kc < 8; kc++) {
        // wait for group kc (leave at most 1 newer group pending)
        if (kc < 7) {
            asm volatile("cp.async.wait_group 1;" ::: "memory");
        } else {
            asm volatile("cp.async.wait_group 0;" ::: "memory");
        }
        __syncthreads();   // stage kc visible to all; all warps done reading kc-1

        // issue load kc+2 into buffer (kc+2)%3 == (kc-1)%3 (safe after sync)
        if (kc + 2 < 8) load_stage(kc + 2, (kc + 2) % 3);

        uint32_t sb = smb + (kc % 3) * GSTAGE;
#pragma unroll
        for (int ks = 0; ks < 4; ks++) {
            uint32_t ah[2][4], al[2][4];
#pragma unroll
            for (int am = 0; am < 2; am++) {
                int mrow = wm + am * 16 + (g & 1) * 8 + lr;
                int kb = ks * 16 + (g >> 1) * 8;
                uint32_t off = SWZ128((uint32_t)(mrow * 128 + kb * 2));
                ldsm_x4(ah[am], sb + off);
                ldsm_x4(al[am], sb + 16384 + off);
            }
            uint32_t bh[4][4], blf[4][4];
#pragma unroll
            for (int bb = 0; bb < 4; bb++) {
                int nrow = wn + bb * 16 + (g >> 1) * 8 + lr;
                int kb = ks * 16 + (g & 1) * 8;
                uint32_t off = SWZ128((uint32_t)(nrow * 128 + kb * 2));
                ldsm_x4(bh[bb],  sb + 32768 + off);
                ldsm_x4(blf[bb], sb + 49152 + off);
            }
#pragma unroll
            for (int am = 0; am < 2; am++)
#pragma unroll
                for (int bb = 0; bb < 4; bb++)
#pragma unroll
                    for (int h = 0; h < 2; h++) {
                        float* c = acc[am][bb * 2 + h];
                        mma16816(c, ah[am], &bh[bb][h * 2]);
                        mma16816(c, ah[am], &blf[bb][h * 2]);
                        mma16816(c, al[am], &bh[bb][h * 2]);
                    }
        }
    }

    // ---- epilogue: +bias, store fp32 ----
    const int n_base = bn * 128 + wn;
#pragma unroll
    for (int am = 0; am < 2; am++) {
        int row = bm * 128 + wm + am * 16 + (lane >> 2);
#pragma unroll
        for (int b8 = 0; b8 < 8; b8++) {
            int n0 = n_base + b8 * 8 + (lane & 3) * 2;
            float bx = bias[n0], by = bias[n0 + 1];
            float* c = acc[am][b8];
            float2 v0 = make_float2(c[0] + bx, c[1] + by);
            float2 v1 = make_float2(c[2] + bx, c[3] + by);
            *(float2*)(g_xpre + (size_t)row * 512 + n0) = v0;
            *(float2*)(g_xpre + (size_t)(row + 8) * 512 + n0) = v1;
        }
    }
}

// ============================================================
// Kernel 2: persistent time scan v6b (verified R11, unchanged)
// ============================================================
#define WSS 92                                   // smem weight stride (floats)
#define SC_W    0                                // [512 cols][92]
#define SC_H    (512 * WSS)                      // 2 parities x 2 batches x 132
#define SMEM2_FLOATS (SC_H + 2 * 2 * 132 + 32)
#define SMEM2_BYTES  (SMEM2_FLOATS * 4)

__global__ __launch_bounds__(256, 1)
void lstm_scan_kernel(const float* __restrict__ c0,
                      const float* __restrict__ h0,
                      const int* __restrict__ done,   // jnp.bool_ arrives as int32
                      const float* __restrict__ Wh,   // [128][512]
                      float* __restrict__ out)
{
    extern __shared__ float smemf[];
    float* wsm = smemf + SC_W;       // wsm[col*WSS + (k-40)], k=40..127
    float* hbb = smemf + SC_H;       // [par][bl][132]

    const int tid = threadIdx.x;
    const int blk = blockIdx.x;
    const int jp  = tid >> 1;                    // hidden unit (lane-pair shared)
    const int bl  = tid & 1;                     // batch lane 0/1
    const int bg  = blk * 2 + bl;                // global batch

    for (int i = tid; i < 88 * 512; i += 256) {
        int kp = i >> 9, col = i & 511;
        wsm[col * WSS + kp] = Wh[(40 + kp) * 512 + col];
    }

    ull wreg2[4][20];
#pragma unroll
    for (int c = 0; c < 4; c++) {
        const int col = jp + 128 * c;
#pragma unroll
        for (int k = 0; k < 40; k += 2)
            wreg2[c][k >> 1] = fpack2(Wh[k * 512 + col], Wh[(k + 1) * 512 + col]);
    }

    hbb[0 * 264 + bl * 132 + jp] = h0[bg * 128 + jp];

    float c_reg = c0[bg * 128 + jp];
    float hlast = 0.0f;

    __syncthreads();

    float x0, x1, x2, x3;
    int dv;
    {
        const float* xp = g_xpre + (size_t)bg * 512;
        x0 = xp[jp]; x1 = xp[128 + jp]; x2 = xp[256 + jp]; x3 = xp[384 + jp];
        dv = done[bg];
    }

    for (int t = 0; t < T_STEPS; t++) {
        float nx0 = 0.f, nx1 = 0.f, nx2 = 0.f, nx3 = 0.f;
        int ndv = 0;
        if (t + 1 < T_STEPS) {
            const float* xp = g_xpre + ((size_t)(t + 1) * BATCH + bg) * 512;
            nx0 = xp[jp]; nx1 = xp[128 + jp]; nx2 = xp[256 + jp]; nx3 = xp[384 + jp];
            ndv = done[(t + 1) * BATCH + bg];
        }

        const float* hb = hbb + (t & 1) * 264 + bl * 132;
        const float keep = dv ? 0.0f : 1.0f;
        float r0 = 0.f, r1 = 0.f, r2 = 0.f, r3 = 0.f;

        unsigned act = __ballot_sync(0xFFFFFFFFu, dv == 0);
        if (act) {
            ull a0 = 0, a1 = 0, a2 = 0, a3 = 0;
            ull b0 = 0, b1 = 0, b2 = 0, b3 = 0;
#pragma unroll
            for (int k = 0; k < 40; k += 4) {
                ulonglong2 hv = *(const ulonglong2*)&hb[k];
                a0 = ffma2(hv.x, wreg2[0][k >> 1], a0);
                a1 = ffma2(hv.x, wreg2[1][k >> 1], a1);
                a2 = ffma2(hv.x, wreg2[2][k >> 1], a2);
                a3 = ffma2(hv.x, wreg2[3][k >> 1], a3);
                a0 = ffma2(hv.y, wreg2[0][(k >> 1) + 1], a0);
                a1 = ffma2(hv.y, wreg2[1][(k >> 1) + 1], a1);
                a2 = ffma2(hv.y, wreg2[2][(k >> 1) + 1], a2);
                a3 = ffma2(hv.y, wreg2[3][(k >> 1) + 1], a3);
            }
#pragma unroll
            for (int k = 40; k < 64; k += 4) {
                ulonglong2 hv = *(const ulonglong2*)&hb[k];
                ulonglong2 w0 = *(const ulonglong2*)&wsm[(jp      ) * WSS + (k - 40)];
                ulonglong2 w1 = *(const ulonglong2*)&wsm[(jp + 128) * WSS + (k - 40)];
                ulonglong2 w2 = *(const ulonglong2*)&wsm[(jp + 256) * WSS + (k - 40)];
                ulonglong2 w3 = *(const ulonglong2*)&wsm[(jp + 384) * WSS + (k - 40)];
                a0 = ffma2(hv.x, w0.x, a0);
                a1 = ffma2(hv.x, w1.x, a1);
                a2 = ffma2(hv.x, w2.x, a2);
                a3 = ffma2(hv.x, w3.x, a3);
                a0 = ffma2(hv.y, w0.y, a0);
                a1 = ffma2(hv.y, w1.y, a1);
                a2 = ffma2(hv.y, w2.y, a2);
                a3 = ffma2(hv.y, w3.y, a3);
            }
#pragma unroll
            for (int k = 64; k < 128; k += 4) {
                ulonglong2 hv = *(const ulonglong2*)&hb[k];
                ulonglong2 w0 = *(const ulonglong2*)&wsm[(jp      ) * WSS + (k - 40)];
                ulonglong2 w1 = *(const ulonglong2*)&wsm[(jp + 128) * WSS + (k - 40)];
                ulonglong2 w2 = *(const ulonglong2*)&wsm[(jp + 256) * WSS + (k - 40)];
                ulonglong2 w3 = *(const ulonglong2*)&wsm[(jp + 384) * WSS + (k - 40)];
                b0 = ffma2(hv.x, w0.x, b0);
                b1 = ffma2(hv.x, w1.x, b1);
                b2 = ffma2(hv.x, w2.x, b2);
                b3 = ffma2(hv.x, w3.x, b3);
                b0 = ffma2(hv.y, w0.y, b0);
                b1 = ffma2(hv.y, w1.y, b1);
                b2 = ffma2(hv.y, w2.y, b2);
                b3 = ffma2(hv.y, w3.y, b3);
            }
            r0 = funpack_add(fadd2(a0, b0));
            r1 = funpack_add(fadd2(a1, b1));
            r2 = funpack_add(fadd2(a2, b2));
            r3 = funpack_add(fadd2(a3, b3));
        }

        float gi = fmaf(keep, r0, x0);
        float gf = fmaf(keep, r1, x1);
        float gg = fmaf(keep, r2, x2);
        float go = fmaf(keep, r3, x3);

        float cprev = keep * c_reg;
        float nc = sigm_(gf) * cprev + sigm_(gi) * tanh_(gg);
        float nh = sigm_(go) * tanh_(nc);
        c_reg = nc;
        hlast = nh;
        out[(size_t)(t * BATCH + bg) * 128 + jp] = nh;
        hbb[((t + 1) & 1) * 264 + bl * 132 + jp] = nh;

        __syncthreads();

        x0 = nx0; x1 = nx1; x2 = nx2; x3 = nx3;
        dv = ndv;
    }

    out[(size_t)YS_ELEMS + bg * 128 + jp] = c_reg;
    out[(size_t)YS_ELEMS + BATCH * HID + bg * 128 + jp] = hlast;
}

// ============================================================
extern "C" void kernel_launch(void* const* d_in, const int* in_sizes, int n_in,
                              void* d_out, int out_size)
{
    const float* c0   = (const float*)d_in[0];
    const float* h0   = (const float*)d_in[1];
    const float* obs  = (const float*)d_in[2];
    const int*   done = (const int*)d_in[3];       // jnp.bool_ -> int32
    const float* Wi   = (const float*)d_in[4];
    const float* Wh   = (const float*)d_in[5];
    const float* bias = (const float*)d_in[6];
    float* out = (float*)d_out;

    cudaFuncSetAttribute(gemm_hmma_kernel,
                         cudaFuncAttributeMaxDynamicSharedMemorySize, GSM_TOTAL);
    cudaFuncSetAttribute(lstm_scan_kernel,
                         cudaFuncAttributeMaxDynamicSharedMemorySize, SMEM2_BYTES);

    split_obs_kernel<<<1024, 256>>>(obs);
    split_wiT_kernel<<<1024, 256>>>(Wi);
    dim3 gg(4, 1024);
    gemm_hmma_kernel<<<gg, 256, GSM_TOTAL>>>(bias);
    lstm_scan_kernel<<<128, 256, SMEM2_BYTES>>>(c0, h0, done, Wh, out);
}

// round 14
// speedup vs baseline: 1.0184x; 1.0184x over previous
#include <cuda_runtime.h>
#include <cuda_bf16.h>
#include <cstdint>

// Problem constants
#define T_STEPS 512
#define BATCH   256
#define D_IN    512
#define HID     128
#define G4      512   // 4*H
#define YS_ELEMS (T_STEPS * BATCH * HID)
#define M_TOTAL  (T_STEPS * BATCH)        // 131072

typedef unsigned long long ull;

// ---------------- device scratch (static; allowed) ----------------
__device__ float          g_xpre  [(size_t)M_TOTAL * G4];      // 256 MB
__device__ __nv_bfloat16  g_obs_hi[(size_t)M_TOTAL * D_IN];    // 128 MB
__device__ __nv_bfloat16  g_obs_lo[(size_t)M_TOTAL * D_IN];    // 128 MB
__device__ __nv_bfloat16  g_wiT_hi[(size_t)G4 * D_IN];         // [n][k]
__device__ __nv_bfloat16  g_wiT_lo[(size_t)G4 * D_IN];

// ---------------- small helpers ----------------
__device__ __forceinline__ ull fpack2(float lo, float hi) {
    ull r; asm("mov.b64 %0, {%1, %2};" : "=l"(r) : "f"(lo), "f"(hi)); return r;
}
__device__ __forceinline__ ull ffma2(ull a, ull b, ull c) {
    ull d; asm("fma.rn.f32x2 %0, %1, %2, %3;" : "=l"(d) : "l"(a), "l"(b), "l"(c)); return d;
}
__device__ __forceinline__ ull fadd2(ull a, ull b) {
    ull d; asm("add.rn.f32x2 %0, %1, %2;" : "=l"(d) : "l"(a), "l"(b)); return d;
}
__device__ __forceinline__ float funpack_add(ull p) {
    float lo, hi; asm("mov.b64 {%0, %1}, %2;" : "=f"(lo), "=f"(hi) : "l"(p));
    return lo + hi;
}
__device__ __forceinline__ float sigm_(float x) {
    return __fdividef(1.0f, 1.0f + __expf(-x));
}
__device__ __forceinline__ float tanh_(float x) {
    float e = __expf(-2.0f * x);
    return __fdividef(1.0f - e, 1.0f + e);
}
__device__ __forceinline__ uint32_t smem_u32(const void* p) {
    uint32_t a;
    asm("{ .reg .u64 t; cvta.to.shared.u64 t, %1; cvt.u32.u64 %0, t; }" : "=r"(a) : "l"(p));
    return a;
}

// SW128 swizzle (byte offsets within a 128B-row tile)
#define SWZ128(o) ((o) ^ (((o) >> 3) & 0x70))

__device__ __forceinline__ void cpasync16(uint32_t s, const void* g) {
    asm volatile("cp.async.cg.shared.global [%0], [%1], 16;" :: "r"(s), "l"(g));
}
__device__ __forceinline__ void ldsm_x4(uint32_t* r, uint32_t addr) {
    asm volatile("ldmatrix.sync.aligned.m8n8.x4.shared.b16 {%0,%1,%2,%3}, [%4];"
        : "=r"(r[0]), "=r"(r[1]), "=r"(r[2]), "=r"(r[3]) : "r"(addr));
}
__device__ __forceinline__ void mma16816(float* c, const uint32_t* a, const uint32_t* b) {
    asm volatile("mma.sync.aligned.m16n8k16.row.col.f32.bf16.bf16.f32 "
        "{%0,%1,%2,%3}, {%4,%5,%6,%7}, {%8,%9}, {%0,%1,%2,%3};"
        : "+f"(c[0]), "+f"(c[1]), "+f"(c[2]), "+f"(c[3])
        : "r"(a[0]), "r"(a[1]), "r"(a[2]), "r"(a[3]), "r"(b[0]), "r"(b[1]));
}

// ============================================================
// Prep 1: split obs fp32 -> bf16 hi/lo (pure bandwidth)
// ============================================================
__global__ __launch_bounds__(256)
void split_obs_kernel(const float* __restrict__ obs) {
    size_t n4 = (size_t)M_TOTAL * D_IN / 4;
    size_t stride = (size_t)gridDim.x * blockDim.x;
    for (size_t i = (size_t)blockIdx.x * blockDim.x + threadIdx.x; i < n4; i += stride) {
        float4 v = ((const float4*)obs)[i];
        __nv_bfloat16 h0 = __float2bfloat16(v.x);
        __nv_bfloat16 h1 = __float2bfloat16(v.y);
        __nv_bfloat16 h2 = __float2bfloat16(v.z);
        __nv_bfloat16 h3 = __float2bfloat16(v.w);
        __nv_bfloat16 l0 = __float2bfloat16(v.x - __bfloat162float(h0));
        __nv_bfloat16 l1 = __float2bfloat16(v.y - __bfloat162float(h1));
        __nv_bfloat16 l2 = __float2bfloat16(v.z - __bfloat162float(h2));
        __nv_bfloat16 l3 = __float2bfloat16(v.w - __bfloat162float(h3));
        ((__nv_bfloat162*)g_obs_hi)[2 * i]     = __nv_bfloat162(h0, h1);
        ((__nv_bfloat162*)g_obs_hi)[2 * i + 1] = __nv_bfloat162(h2, h3);
        ((__nv_bfloat162*)g_obs_lo)[2 * i]     = __nv_bfloat162(l0, l1);
        ((__nv_bfloat162*)g_obs_lo)[2 * i + 1] = __nv_bfloat162(l2, l3);
    }
}

// ============================================================
// Prep 2: transpose + split Wi [k][n] -> WiT hi/lo [n][k]
// ============================================================
__global__ __launch_bounds__(256)
void split_wiT_kernel(const float* __restrict__ Wi) {
    int idx = blockIdx.x * blockDim.x + threadIdx.x;
    if (idx < G4 * D_IN) {
        int n = idx >> 9, k = idx & 511;
        float v = Wi[k * G4 + n];
        __nv_bfloat16 h = __float2bfloat16(v);
        __nv_bfloat16 l = __float2bfloat16(v - __bfloat162float(h));
        g_wiT_hi[idx] = h;
        g_wiT_lo[idx] = l;
    }
}

// ============================================================
// GEMM via mma.sync bf16-split (Ah*Bh + Ah*Bl + Al*Bh, fp32 acc)
// v4: all-cp.async (R5 structure), BN=64 -> 48KB/stage, 96KB
//     total -> 2 CTAs/SM (16 warps) for HMMA latency cover.
//     Warp tile 32m x 32n; A traffic duplicated (DRAM is idle).
// ============================================================
// stage layout: Ah 16K | Al 16K | Bh 8K | Bl 8K
#define GS_AH 0
#define GS_AL 16384
#define GS_BH 32768
#define GS_BL 40960
#define GSTAGE 49152
#define GSM_TOTAL (2 * GSTAGE)     // 98304

__global__ __launch_bounds__(256, 2)
void gemm_hmma_kernel(const float* __restrict__ bias)
{
    extern __shared__ __align__(1024) char smem[];
    const uint32_t smb = smem_u32(smem);
    const int tid = threadIdx.x;
    const int warp = tid >> 5, lane = tid & 31;
    const int bn = blockIdx.x;     // 0..7  (BN=64)
    const int bm = blockIdx.y;     // 0..1023

    const __nv_bfloat16* Agh = g_obs_hi + (size_t)bm * 128 * 512;
    const __nv_bfloat16* Agl = g_obs_lo + (size_t)bm * 128 * 512;
    const __nv_bfloat16* Bgh = g_wiT_hi + (size_t)bn * 64 * 512;
    const __nv_bfloat16* Bgl = g_wiT_lo + (size_t)bn * 64 * 512;

    auto load_stage = [&](int kc, int s) {
        uint32_t sb = smb + s * GSTAGE;
        // A tiles: 128 rows x 64 k x bf16 = 16KB each (hi, lo)
#pragma unroll
        for (int t = 0; t < 4; t++) {
            int i = tid + t * 256;
            int row = i >> 3, cc = i & 7;
            uint32_t so = SWZ128((uint32_t)(row * 128 + cc * 16));
            cpasync16(sb + GS_AH + so, Agh + (size_t)row * 512 + kc * 64 + cc * 8);
            cpasync16(sb + GS_AL + so, Agl + (size_t)row * 512 + kc * 64 + cc * 8);
        }
        // B tiles: 64 n-rows x 64 k x bf16 = 8KB each (hi, lo)
#pragma unroll
        for (int t = 0; t < 2; t++) {
            int i = tid + t * 256;
            int row = i >> 3, cc = i & 7;
            uint32_t so = SWZ128((uint32_t)(row * 128 + cc * 16));
            cpasync16(sb + GS_BH + so, Bgh + (size_t)row * 512 + kc * 64 + cc * 8);
            cpasync16(sb + GS_BL + so, Bgl + (size_t)row * 512 + kc * 64 + cc * 8);
        }
        asm volatile("cp.async.commit_group;" ::: "memory");
    };

    const int wm = (warp & 3) * 32;        // 0..96
    const int wn = (warp >> 2) * 32;       // 0 or 32
    const int lr = lane & 7, g = lane >> 3;

    float acc[2][4][4];
#pragma unroll
    for (int i = 0; i < 2; i++)
#pragma unroll
        for (int j = 0; j < 4; j++)
#pragma unroll
            for (int q = 0; q < 4; q++) acc[i][j][q] = 0.0f;

    load_stage(0, 0);

    for (int kc = 0; kc < 8; kc++) {
        if (kc + 1 < 8) {
            load_stage(kc + 1, (kc + 1) & 1);
            asm volatile("cp.async.wait_group 1;" ::: "memory");
        } else {
            asm volatile("cp.async.wait_group 0;" ::: "memory");
        }
        __syncthreads();

        uint32_t sb = smb + (kc & 1) * GSTAGE;
#pragma unroll
        for (int ks = 0; ks < 4; ks++) {
            uint32_t ah[2][4], al[2][4];
#pragma unroll
            for (int am = 0; am < 2; am++) {
                int mrow = wm + am * 16 + (g & 1) * 8 + lr;
                int kb = ks * 16 + (g >> 1) * 8;
                uint32_t off = SWZ128((uint32_t)(mrow * 128 + kb * 2));
                ldsm_x4(ah[am], sb + GS_AH + off);
                ldsm_x4(al[am], sb + GS_AL + off);
            }
            uint32_t bh[2][4], blf[2][4];
#pragma unroll
            for (int bb = 0; bb < 2; bb++) {
                int nrow = wn + bb * 16 + (g >> 1) * 8 + lr;
                int kb = ks * 16 + (g & 1) * 8;
                uint32_t off = SWZ128((uint32_t)(nrow * 128 + kb * 2));
                ldsm_x4(bh[bb],  sb + GS_BH + off);
                ldsm_x4(blf[bb], sb + GS_BL + off);
            }
#pragma unroll
            for (int am = 0; am < 2; am++)
#pragma unroll
                for (int bb = 0; bb < 2; bb++)
#pragma unroll
                    for (int h = 0; h < 2; h++) {
                        float* c = acc[am][bb * 2 + h];
                        mma16816(c, ah[am], &bh[bb][h * 2]);
                        mma16816(c, ah[am], &blf[bb][h * 2]);
                        mma16816(c, al[am], &bh[bb][h * 2]);
                    }
        }
        __syncthreads();
    }

    // ---- epilogue: +bias, store fp32 ----
    const int n_base = bn * 64 + wn;
#pragma unroll
    for (int am = 0; am < 2; am++) {
        int row = bm * 128 + wm + am * 16 + (lane >> 2);
#pragma unroll
        for (int b8 = 0; b8 < 4; b8++) {
            int n0 = n_base + b8 * 8 + (lane & 3) * 2;
            float bx = bias[n0], by = bias[n0 + 1];
            float* c = acc[am][b8];
            float2 v0 = make_float2(c[0] + bx, c[1] + by);
            float2 v1 = make_float2(c[2] + bx, c[3] + by);
            *(float2*)(g_xpre + (size_t)row * 512 + n0) = v0;
            *(float2*)(g_xpre + (size_t)(row + 8) * 512 + n0) = v1;
        }
    }
}

// ============================================================
// Kernel 2: persistent time scan v6b (verified R11/R13, unchanged)
// ============================================================
#define WSS 92                                   // smem weight stride (floats)
#define SC_W    0                                // [512 cols][92]
#define SC_H    (512 * WSS)                      // 2 parities x 2 batches x 132
#define SMEM2_FLOATS (SC_H + 2 * 2 * 132 + 32)
#define SMEM2_BYTES  (SMEM2_FLOATS * 4)

__global__ __launch_bounds__(256, 1)
void lstm_scan_kernel(const float* __restrict__ c0,
                      const float* __restrict__ h0,
                      const int* __restrict__ done,   // jnp.bool_ arrives as int32
                      const float* __restrict__ Wh,   // [128][512]
                      float* __restrict__ out)
{
    extern __shared__ float smemf[];
    float* wsm = smemf + SC_W;       // wsm[col*WSS + (k-40)], k=40..127
    float* hbb = smemf + SC_H;       // [par][bl][132]

    const int tid = threadIdx.x;
    const int blk = blockIdx.x;
    const int jp  = tid >> 1;                    // hidden unit (lane-pair shared)
    const int bl  = tid & 1;                     // batch lane 0/1
    const int bg  = blk * 2 + bl;                // global batch

    for (int i = tid; i < 88 * 512; i += 256) {
        int kp = i >> 9, col = i & 511;
        wsm[col * WSS + kp] = Wh[(40 + kp) * 512 + col];
    }

    ull wreg2[4][20];
#pragma unroll
    for (int c = 0; c < 4; c++) {
        const int col = jp + 128 * c;
#pragma unroll
        for (int k = 0; k < 40; k += 2)
            wreg2[c][k >> 1] = fpack2(Wh[k * 512 + col], Wh[(k + 1) * 512 + col]);
    }

    hbb[0 * 264 + bl * 132 + jp] = h0[bg * 128 + jp];

    float c_reg = c0[bg * 128 + jp];
    float hlast = 0.0f;

    __syncthreads();

    float x0, x1, x2, x3;
    int dv;
    {
        const float* xp = g_xpre + (size_t)bg * 512;
        x0 = xp[jp]; x1 = xp[128 + jp]; x2 = xp[256 + jp]; x3 = xp[384 + jp];
        dv = done[bg];
    }

    for (int t = 0; t < T_STEPS; t++) {
        float nx0 = 0.f, nx1 = 0.f, nx2 = 0.f, nx3 = 0.f;
        int ndv = 0;
        if (t + 1 < T_STEPS) {
            const float* xp = g_xpre + ((size_t)(t + 1) * BATCH + bg) * 512;
            nx0 = xp[jp]; nx1 = xp[128 + jp]; nx2 = xp[256 + jp]; nx3 = xp[384 + jp];
            ndv = done[(t + 1) * BATCH + bg];
        }

        const float* hb = hbb + (t & 1) * 264 + bl * 132;
        const float keep = dv ? 0.0f : 1.0f;
        float r0 = 0.f, r1 = 0.f, r2 = 0.f, r3 = 0.f;

        unsigned act = __ballot_sync(0xFFFFFFFFu, dv == 0);
        if (act) {
            ull a0 = 0, a1 = 0, a2 = 0, a3 = 0;
            ull b0 = 0, b1 = 0, b2 = 0, b3 = 0;
#pragma unroll
            for (int k = 0; k < 40; k += 4) {
                ulonglong2 hv = *(const ulonglong2*)&hb[k];
                a0 = ffma2(hv.x, wreg2[0][k >> 1], a0);
                a1 = ffma2(hv.x, wreg2[1][k >> 1], a1);
                a2 = ffma2(hv.x, wreg2[2][k >> 1], a2);
                a3 = ffma2(hv.x, wreg2[3][k >> 1], a3);
                a0 = ffma2(hv.y, wreg2[0][(k >> 1) + 1], a0);
                a1 = ffma2(hv.y, wreg2[1][(k >> 1) + 1], a1);
                a2 = ffma2(hv.y, wreg2[2][(k >> 1) + 1], a2);
                a3 = ffma2(hv.y, wreg2[3][(k >> 1) + 1], a3);
            }
#pragma unroll
            for (int k = 40; k < 64; k += 4) {
                ulonglong2 hv = *(const ulonglong2*)&hb[k];
                ulonglong2 w0 = *(const ulonglong2*)&wsm[(jp      ) * WSS + (k - 40)];
                ulonglong2 w1 = *(const ulonglong2*)&wsm[(jp + 128) * WSS + (k - 40)];
                ulonglong2 w2 = *(const ulonglong2*)&wsm[(jp + 256) * WSS + (k - 40)];
                ulonglong2 w3 = *(const ulonglong2*)&wsm[(jp + 384) * WSS + (k - 40)];
                a0 = ffma2(hv.x, w0.x, a0);
                a1 = ffma2(hv.x, w1.x, a1);
                a2 = ffma2(hv.x, w2.x, a2);
                a3 = ffma2(hv.x, w3.x, a3);
                a0 = ffma2(hv.y, w0.y, a0);
                a1 = ffma2(hv.y, w1.y, a1);
                a2 = ffma2(hv.y, w2.y, a2);
                a3 = ffma2(hv.y, w3.y, a3);
            }
#pragma unroll
            for (int k = 64; k < 128; k += 4) {
                ulonglong2 hv = *(const ulonglong2*)&hb[k];
                ulonglong2 w0 = *(const ulonglong2*)&wsm[(jp      ) * WSS + (k - 40)];
                ulonglong2 w1 = *(const ulonglong2*)&wsm[(jp + 128) * WSS + (k - 40)];
                ulonglong2 w2 = *(const ulonglong2*)&wsm[(jp + 256) * WSS + (k - 40)];
                ulonglong2 w3 = *(const ulonglong2*)&wsm[(jp + 384) * WSS + (k - 40)];
                b0 = ffma2(hv.x, w0.x, b0);
                b1 = ffma2(hv.x, w1.x, b1);
                b2 = ffma2(hv.x, w2.x, b2);
                b3 = ffma2(hv.x, w3.x, b3);
                b0 = ffma2(hv.y, w0.y, b0);
                b1 = ffma2(hv.y, w1.y, b1);
                b2 = ffma2(hv.y, w2.y, b2);
                b3 = ffma2(hv.y, w3.y, b3);
            }
            r0 = funpack_add(fadd2(a0, b0));
            r1 = funpack_add(fadd2(a1, b1));
            r2 = funpack_add(fadd2(a2, b2));
            r3 = funpack_add(fadd2(a3, b3));
        }

        float gi = fmaf(keep, r0, x0);
        float gf = fmaf(keep, r1, x1);
        float gg = fmaf(keep, r2, x2);
        float go = fmaf(keep, r3, x3);

        float cprev = keep * c_reg;
        float nc = sigm_(gf) * cprev + sigm_(gi) * tanh_(gg);
        float nh = sigm_(go) * tanh_(nc);
        c_reg = nc;
        hlast = nh;
        out[(size_t)(t * BATCH + bg) * 128 + jp] = nh;
        hbb[((t + 1) & 1) * 264 + bl * 132 + jp] = nh;

        __syncthreads();

        x0 = nx0; x1 = nx1; x2 = nx2; x3 = nx3;
        dv = ndv;
    }

    out[(size_t)YS_ELEMS + bg * 128 + jp] = c_reg;
    out[(size_t)YS_ELEMS + BATCH * HID + bg * 128 + jp] = hlast;
}

// ============================================================
extern "C" void kernel_launch(void* const* d_in, const int* in_sizes, int n_in,
                              void* d_out, int out_size)
{
    const float* c0   = (const float*)d_in[0];
    const float* h0   = (const float*)d_in[1];
    const float* obs  = (const float*)d_in[2];
    const int*   done = (const int*)d_in[3];       // jnp.bool_ -> int32
    const float* Wi   = (const float*)d_in[4];
    const float* Wh   = (const float*)d_in[5];
    const float* bias = (const float*)d_in[6];
    float* out = (float*)d_out;

    cudaFuncSetAttribute(gemm_hmma_kernel,
                         cudaFuncAttributeMaxDynamicSharedMemorySize, GSM_TOTAL);
    cudaFuncSetAttribute(lstm_scan_kernel,
                         cudaFuncAttributeMaxDynamicSharedMemorySize, SMEM2_BYTES);

    split_obs_kernel<<<1024, 256>>>(obs);
    split_wiT_kernel<<<1024, 256>>>(Wi);
    dim3 gg(8, 1024);
    gemm_hmma_kernel<<<gg, 256, GSM_TOTAL>>>(bias);
    lstm_scan_kernel<<<128, 256, SMEM2_BYTES>>>(c0, h0, done, Wh, out);
}